// round 1
// baseline (speedup 1.0000x reference)
#include <cuda_runtime.h>
#include <math.h>

#define B_    8
#define T_    8
#define C_    256
#define CH_   64
#define Wd    56
#define HW_   3136
#define PTILE 112
#define NPB   28          // HW_/PTILE

// ---------------- scratch (device globals; no allocation allowed) ----------------
__device__ float g_maxavg[(size_t)B_ * T_ * 2 * HW_];   // (BT,2,HW)  1.6MB
__device__ float g_gate[(size_t)B_ * T_ * HW_];         // (BT,HW)    0.8MB
__device__ float g_wr[C_ * 3 * CH_];                    // w_reduce transposed: [(c*3+dt)*64+ch]
__device__ float g_we[CH_ * C_];                        // w_expand transposed: [cin*256+cout]
__device__ float g_t[(size_t)B_ * CH_ * T_ * HW_];      // (B,64,T,HW) 51MB
__device__ float g_xt[(size_t)B_ * C_ * T_ * HW_];      // (B,C,T,HW)  205MB
__device__ float g_vpart[(size_t)B_ * C_ * T_ * NPB];   // per-block pixel-sum partials (deterministic)
__device__ float g_kern[B_ * C_ * 3];                   // dynamic kernel coeffs

// ---------------- prep: transpose weights for coalesced smem loads ----------------
__global__ void k_prep(const float* __restrict__ wr, const float* __restrict__ we) {
    int idx = blockIdx.x * blockDim.x + threadIdx.x;
    if (idx < C_ * 3 * CH_) {
        int ch = idx & 63;
        int dtc = idx >> 6;           // = c*3+dt
        int c = dtc / 3, dt = dtc % 3;
        g_wr[idx] = wr[ch * (C_ * 3) + c * 3 + dt];   // w_reduce (ch,C,3)
    }
    if (idx < CH_ * C_) {
        int cout = idx & 255;
        int cin = idx >> 8;
        g_we[idx] = we[cout * CH_ + cin];             // w_expand (C,ch)
    }
}

// ---------------- channel max/mean over C ----------------
__global__ __launch_bounds__(256) void k_maxmean(const float* __restrict__ x) {
    int bt = blockIdx.y;
    int p = blockIdx.x * blockDim.x + threadIdx.x;
    if (p >= HW_) return;
    const float* xp = x + (size_t)bt * C_ * HW_ + p;
    float mx = -INFINITY, sm = 0.f;
#pragma unroll 4
    for (int c = 0; c < C_; c++) {
        float v = xp[(size_t)c * HW_];
        mx = fmaxf(mx, v);
        sm += v;
    }
    g_maxavg[(size_t)bt * 2 * HW_ + p] = mx;
    g_maxavg[(size_t)bt * 2 * HW_ + HW_ + p] = sm * (1.f / C_);
}

// ---------------- 7x7 conv on [max,avg] -> spatial gate 1+sigmoid ----------------
__global__ __launch_bounds__(256) void k_spatial(const float* __restrict__ w) {
    __shared__ float sw[98];
    int tid = threadIdx.x;
    if (tid < 98) sw[tid] = w[tid];
    __syncthreads();
    int bt = blockIdx.y;
    int p = blockIdx.x * blockDim.x + tid;
    if (p >= HW_) return;
    int py = p / Wd, px = p % Wd;
    const float* mb = g_maxavg + (size_t)bt * 2 * HW_;
    float s = 0.f;
#pragma unroll
    for (int ky = 0; ky < 7; ky++) {
        int iy = py + ky - 3;
        if (iy < 0 || iy >= Wd) continue;
#pragma unroll
        for (int kx = 0; kx < 7; kx++) {
            int ix = px + kx - 3;
            if (ix < 0 || ix >= Wd) continue;
            float m = mb[iy * Wd + ix];
            float a = mb[HW_ + iy * Wd + ix];
            s += sw[ky * 7 + kx] * m + sw[49 + ky * 7 + kx] * a;
        }
    }
    g_gate[(size_t)bt * HW_ + p] = 1.f + 1.f / (1.f + __expf(-s));
}

// ---------------- fused gated reduce conv3d (GEMM 64xP, K=768) + BN + relu ----------------
// block: (pixel tile of 112, t, b). 256 thr: 16(ch)x16(px), thread tile 4ch x 7px.
__global__ __launch_bounds__(256) void k_reduce(
    const float* __restrict__ x, const float* __restrict__ gamma,
    const float* __restrict__ beta, const float* __restrict__ mean,
    const float* __restrict__ var) {
    __shared__ float sgate[3][PTILE];
    __shared__ float sxs[8][3][PTILE];
    __shared__ float sw[8][192];

    int tid = threadIdx.x;
    int p0 = blockIdx.x * PTILE;
    int t = blockIdx.y, b = blockIdx.z;

    for (int idx = tid; idx < 3 * PTILE; idx += 256) {
        int dt = idx / PTILE, p = idx % PTILE;
        int tin = t + dt - 1;
        sgate[dt][p] = (tin >= 0 && tin < T_)
                           ? g_gate[(size_t)(b * T_ + tin) * HW_ + p0 + p] : 0.f;
    }

    int ty = tid >> 4, tx = tid & 15;
    int chb = ty * 4, pb = tx * 7;
    float acc[4][7];
#pragma unroll
    for (int i = 0; i < 4; i++)
#pragma unroll
        for (int j = 0; j < 7; j++) acc[i][j] = 0.f;

    for (int c0 = 0; c0 < C_; c0 += 8) {
        __syncthreads();   // first iter: covers sgate; later: protect sxs/sw reuse
        for (int idx = tid; idx < 8 * 3 * PTILE; idx += 256) {
            int cc = idx / (3 * PTILE);
            int r = idx % (3 * PTILE);
            int dt = r / PTILE, p = r % PTILE;
            int tin = t + dt - 1;
            float v = 0.f;
            if (tin >= 0 && tin < T_)
                v = x[((size_t)((b * T_ + tin) * C_ + c0 + cc)) * HW_ + p0 + p] * sgate[dt][p];
            sxs[cc][dt][p] = v;
        }
        for (int idx = tid; idx < 8 * 192; idx += 256) {
            int cc = idx / 192, r = idx % 192;
            sw[cc][r] = g_wr[(c0 + cc) * 192 + r];
        }
        __syncthreads();
#pragma unroll
        for (int cc = 0; cc < 8; cc++) {
#pragma unroll
            for (int dt = 0; dt < 3; dt++) {
                float wv[4], xv[7];
#pragma unroll
                for (int i = 0; i < 4; i++) wv[i] = sw[cc][dt * 64 + chb + i];
#pragma unroll
                for (int j = 0; j < 7; j++) xv[j] = sxs[cc][dt][pb + j];
#pragma unroll
                for (int i = 0; i < 4; i++)
#pragma unroll
                    for (int j = 0; j < 7; j++)
                        acc[i][j] = fmaf(wv[i], xv[j], acc[i][j]);
            }
        }
    }
    // BN + relu, write t-buffer (B,64,T,HW)
#pragma unroll
    for (int i = 0; i < 4; i++) {
        int ch = chb + i;
        float inv = gamma[ch] * rsqrtf(var[ch] + 1e-5f);
        float bia = beta[ch] - mean[ch] * inv;
        float* dst = g_t + ((size_t)((b * CH_ + ch) * T_ + t)) * HW_ + p0 + pb;
#pragma unroll
        for (int j = 0; j < 7; j++)
            dst[j] = fmaxf(fmaf(acc[i][j], inv, bia), 0.f);
    }
}

// ---------------- expand 1x1x1 (GEMM 256xP, K=64) + sigmoid + x_t + v partials ----------------
__global__ __launch_bounds__(256) void k_expand(const float* __restrict__ x) {
    __shared__ float st[CH_][PTILE];    // 28KB
    __shared__ float sw2[CH_][CH_];     // 16KB
    __shared__ float sgate[PTILE];
    __shared__ float sred[CH_][16];     // 4KB

    int tid = threadIdx.x;
    int p0 = blockIdx.x * PTILE;
    int t = blockIdx.y, b = blockIdx.z;

    for (int idx = tid; idx < CH_ * PTILE; idx += 256) {
        int ch = idx / PTILE, p = idx % PTILE;
        st[ch][p] = g_t[((size_t)((b * CH_ + ch) * T_ + t)) * HW_ + p0 + p];
    }
    if (tid < PTILE)
        sgate[tid] = g_gate[(size_t)(b * T_ + t) * HW_ + p0 + tid];

    int ty = tid >> 4, tx = tid & 15;
    int chb = ty * 4, pb = tx * 7;

    for (int co = 0; co < 4; co++) {
        __syncthreads();   // covers st/sgate on first iter; protects sw2/sred reuse after
        for (int idx = tid; idx < CH_ * CH_; idx += 256) {
            int cin = idx >> 6, j = idx & 63;
            sw2[cin][j] = g_we[cin * C_ + co * 64 + j];
        }
        __syncthreads();

        float acc[4][7];
#pragma unroll
        for (int i = 0; i < 4; i++)
#pragma unroll
            for (int j = 0; j < 7; j++) acc[i][j] = 0.f;

#pragma unroll 4
        for (int cin = 0; cin < CH_; cin++) {
            float wv[4], xv[7];
#pragma unroll
            for (int i = 0; i < 4; i++) wv[i] = sw2[cin][chb + i];
#pragma unroll
            for (int j = 0; j < 7; j++) xv[j] = st[cin][pb + j];
#pragma unroll
            for (int i = 0; i < 4; i++)
#pragma unroll
                for (int j = 0; j < 7; j++)
                    acc[i][j] = fmaf(wv[i], xv[j], acc[i][j]);
        }

        // epilogue: x_t = x*gate*(1+sigmoid(acc)); write + pixel partial sums
        float psum[4];
#pragma unroll
        for (int i = 0; i < 4; i++) {
            int cout = co * 64 + chb + i;
            const float* xsrc = x + ((size_t)((b * T_ + t) * C_ + cout)) * HW_ + p0 + pb;
            float* dst = g_xt + ((size_t)((b * C_ + cout) * T_ + t)) * HW_ + p0 + pb;
            float s = 0.f;
#pragma unroll
            for (int j = 0; j < 7; j++) {
                float attn = 1.f / (1.f + __expf(-acc[i][j]));
                float xt = xsrc[j] * sgate[pb + j] * (1.f + attn);
                dst[j] = xt;
                s += xt;
            }
            psum[i] = s;
        }
        __syncthreads();
#pragma unroll
        for (int i = 0; i < 4; i++) sred[chb + i][tx] = psum[i];
        __syncthreads();
        if (tid < 64) {
            float s = 0.f;
#pragma unroll
            for (int k = 0; k < 16; k++) s += sred[tid][k];
            int cout = co * 64 + tid;
            g_vpart[((size_t)((b * C_ + cout) * T_ + t)) * NPB + blockIdx.x] = s;
        }
    }
}

// ---------------- dynamic temporal kernel: mean -> fc1 -> relu -> fc2 -> softmax ----------------
__global__ __launch_bounds__(256) void k_dyn(
    const float* __restrict__ wfc1, const float* __restrict__ bfc1,
    const float* __restrict__ wfc2, const float* __restrict__ bfc2) {
    int id = blockIdx.x * blockDim.x + threadIdx.x;
    if (id >= B_ * C_) return;
    float v[T_];
#pragma unroll
    for (int t = 0; t < T_; t++) {
        const float* pp = g_vpart + ((size_t)id * T_ + t) * NPB;
        float s = 0.f;
#pragma unroll
        for (int k = 0; k < NPB; k++) s += pp[k];
        v[t] = s * (1.f / HW_);
    }
    float lg[3] = {bfc2[0], bfc2[1], bfc2[2]};
#pragma unroll
    for (int hh = 0; hh < 16; hh++) {
        float s = bfc1[hh];
#pragma unroll
        for (int t = 0; t < T_; t++) s += wfc1[hh * 8 + t] * v[t];
        s = fmaxf(s, 0.f);
#pragma unroll
        for (int k = 0; k < 3; k++) lg[k] += wfc2[k * 16 + hh] * s;
    }
    float m = fmaxf(lg[0], fmaxf(lg[1], lg[2]));
    float e0 = __expf(lg[0] - m), e1 = __expf(lg[1] - m), e2 = __expf(lg[2] - m);
    float inv = 1.f / (e0 + e1 + e2);
    g_kern[id * 3 + 0] = e0 * inv;
    g_kern[id * 3 + 1] = e1 * inv;
    g_kern[id * 3 + 2] = e2 * inv;
}

// ---------------- depthwise temporal stencil (rolling window over t) ----------------
__global__ __launch_bounds__(256) void k_stencil(float* __restrict__ out) {
    int p = blockIdx.x * blockDim.x + threadIdx.x;
    if (p >= HW_) return;
    int bc = blockIdx.y;
    int b = bc >> 8, c = bc & 255;
    float k0 = g_kern[bc * 3 + 0];
    float k1 = g_kern[bc * 3 + 1];
    float k2 = g_kern[bc * 3 + 2];
    const float* src = g_xt + (size_t)bc * T_ * HW_ + p;
    float prev = 0.f, cur = src[0];
#pragma unroll
    for (int t = 0; t < T_; t++) {
        float nxt = (t < T_ - 1) ? src[(size_t)(t + 1) * HW_] : 0.f;
        out[((size_t)((b * T_ + t) * C_ + c)) * HW_ + p] = k0 * prev + k1 * cur + k2 * nxt;
        prev = cur;
        cur = nxt;
    }
}

// ---------------- launch ----------------
extern "C" void kernel_launch(void* const* d_in, const int* in_sizes, int n_in,
                              void* d_out, int out_size) {
    const float* x      = (const float*)d_in[0];
    const float* w_sp   = (const float*)d_in[1];
    const float* w_red  = (const float*)d_in[2];
    const float* gam    = (const float*)d_in[3];
    const float* bet    = (const float*)d_in[4];
    const float* mea    = (const float*)d_in[5];
    const float* var    = (const float*)d_in[6];
    const float* w_exp  = (const float*)d_in[7];
    const float* wfc1   = (const float*)d_in[8];
    const float* bfc1   = (const float*)d_in[9];
    const float* wfc2   = (const float*)d_in[10];
    const float* bfc2   = (const float*)d_in[11];
    float* out = (float*)d_out;

    k_prep<<<192, 256>>>(w_red, w_exp);
    k_maxmean<<<dim3(13, B_ * T_), 256>>>(x);
    k_spatial<<<dim3(13, B_ * T_), 256>>>(w_sp);
    k_reduce<<<dim3(NPB, T_, B_), 256>>>(x, gam, bet, mea, var);
    k_expand<<<dim3(NPB, T_, B_), 256>>>(x);
    k_dyn<<<8, 256>>>(wfc1, bfc1, wfc2, bfc2);
    k_stencil<<<dim3(13, B_ * C_), 256>>>(out);
}